// round 13
// baseline (speedup 1.0000x reference)
#include <cuda_runtime.h>
#include <math.h>

#define BATCH 4
#define CCH 256
#define HH 160
#define WW 160
#define NV 10
#define NH 10
#define NPATCH 100     // NV*NH
#define ENC 128
#define NROWS (BATCH*NPATCH)   // 400
#define FUSED_BLOCKS 100

// Scratch
__device__ float g_x[2][NROWS * 256];     // conv outputs (patch-flattened)
__device__ float g_e[2][NROWS * ENC];     // embeddings
__device__ float g_w1t[2][256 * 256];     // w1 transposed: [k][col]
__device__ float g_w2t[2][256 * 128];     // w2 transposed: [k][col]
__device__ unsigned g_bar0;               // inter-phase barrier
__device__ unsigned g_bar1;               // exit counter for reset

// ---------------------------------------------------------------------------
// Tiled matrix transpose: out[N][M] = in[M][N]^T.  256 threads, smem tile.
// ---------------------------------------------------------------------------
__device__ void transpose_mat(const float* __restrict__ in, float* __restrict__ out,
                              int M, int N)
{
    __shared__ float tile[32][33];
    int tx = threadIdx.x & 31;
    int ty = threadIdx.x >> 5;          // 0..7
    int ntiles = (M / 32) * (N / 32);
    for (int tt = 0; tt < ntiles; tt++) {
        int m0 = (tt / (N / 32)) * 32;
        int n0 = (tt % (N / 32)) * 32;
        __syncthreads();
        #pragma unroll
        for (int r = ty; r < 32; r += 8)
            tile[r][tx] = in[(m0 + r) * N + n0 + tx];
        __syncthreads();
        #pragma unroll
        for (int r = ty; r < 32; r += 8)
            out[(n0 + r) * M + m0 + tx] = tile[tx][r];
    }
}

// ---------------------------------------------------------------------------
// Kernel A: 1x1 conv (C=256 -> 1) + bias + relu  (HBM-saturated ~6.1 TB/s).
// Blocks 1600..1603 instead transpose the fc weights (hidden under conv).
// ---------------------------------------------------------------------------
__global__ void __launch_bounds__(256) conv_kernel(
    const float* __restrict__ feat1, const float* __restrict__ feat2,
    const float* __restrict__ cw1, const float* __restrict__ cb1,
    const float* __restrict__ cw2, const float* __restrict__ cb2,
    const float* __restrict__ w1a, const float* __restrict__ w1b,
    const float* __restrict__ w2a, const float* __restrict__ w2b)
{
    if (blockIdx.x >= 1600) {
        int which = blockIdx.x - 1600;
        if      (which == 0) transpose_mat(w1a, g_w1t[0], 256, 256);
        else if (which == 1) transpose_mat(w1b, g_w1t[1], 256, 256);
        else if (which == 2) transpose_mat(w2a, g_w2t[0], 128, 256);
        else                 transpose_mat(w2b, g_w2t[1], 128, 256);
        return;
    }

    __shared__ float  cw[CCH];
    __shared__ float4 part[256];

    int o0 = blockIdx.x * 32;
    int f  = o0 / 25600;
    const float* feat = f ? feat2 : feat1;
    if (threadIdx.x < CCH) cw[threadIdx.x] = (f ? cw2 : cw1)[threadIdx.x];
    __syncthreads();

    int wi    = threadIdx.x & 31;
    int chunk = threadIdx.x >> 5;

    int rem = (o0 + wi) % 25600;
    int b   = rem / 6400;
    int r2  = rem % 6400;
    int h   = r2 / 40;
    int w0  = (r2 % 40) * 4;

    const int cstride = HH * WW / 4;
    const float4* src = (const float4*)(feat + (size_t)b * CCH * HH * WW + h * WW + w0)
                        + (size_t)chunk * 32 * cstride;

    float4 acc = make_float4(0.f, 0.f, 0.f, 0.f);
    #pragma unroll
    for (int c = 0; c < 32; c++) {
        float4 v = src[c * cstride];
        float wv = cw[chunk * 32 + c];
        acc.x = fmaf(v.x, wv, acc.x);
        acc.y = fmaf(v.y, wv, acc.y);
        acc.z = fmaf(v.z, wv, acc.z);
        acc.w = fmaf(v.w, wv, acc.w);
    }
    part[threadIdx.x] = acc;
    __syncthreads();

    if (threadIdx.x < 32) {
        float4 a = part[threadIdx.x];
        #pragma unroll
        for (int k = 1; k < 8; k++) {
            float4 p = part[threadIdx.x + k * 32];
            a.x += p.x; a.y += p.y; a.z += p.z; a.w += p.w;
        }
        float cb = f ? cb2[0] : cb1[0];
        a.x = fmaxf(a.x + cb, 0.f);
        a.y = fmaxf(a.y + cb, 0.f);
        a.z = fmaxf(a.z + cb, 0.f);
        a.w = fmaxf(a.w + cb, 0.f);

        int p   = b * NPATCH + (h >> 4) * NH + (w0 >> 4);
        int idx = (h & 15) * 16 + (w0 & 15);
        *(float4*)&g_x[f][p * 256 + idx] = a;
    }
}

// ---------------------------------------------------------------------------
// Kernel B (fused, 512 threads): fc1 + fc2 + LN | grid barrier | logits.
// Coalesced weight reads via transposed weights: thread = (col-pair, K-split),
// warp lanes = consecutive col-pairs -> weight LDG.64 is 256B/warp (2 wf,
// 16x fewer L1 wavefronts than the thread-per-col layout).
// smem pool 48KB: xs[0:2048) hs[2048:4096) ps[4096:12288)
//   phase2: e1s pool[0:512), e2s pool[1024:7824)
// ---------------------------------------------------------------------------
__global__ void __launch_bounds__(512) fused_kernel(
    const float* __restrict__ ga,  const float* __restrict__ ba,
    const float* __restrict__ gb,  const float* __restrict__ bb,
    const float* __restrict__ lsc, float* __restrict__ out)
{
    __shared__ float pool[12288];   // 48 KB

    float* xs = pool;               // 8 x 256
    float* hs = pool + 2048;        // 8 x 256
    float* ps = pool + 4096;        // partials: 4x[8][256] (s1) / 8x[8][128] (s2)
    float* ys = pool;               // fc2 out 8x128 (aliases xs, dead by then)

    int t   = threadIdx.x;
    int bid = blockIdx.x;           // 0..99

    // ---------------- Phase 1: FC + LayerNorm ----------------
    {
        int br = bid / 50;
        int r0 = (bid % 50) * 8;
        const float* lng = br ? gb : ga;
        const float* lnb = br ? bb : ba;
        const float* w1t = g_w1t[br];
        const float* w2t = g_w2t[br];

        // load 8x256 input rows (512 float4, 1 per thread)
        ((float4*)xs)[t] = ((const float4*)(g_x[br] + r0 * 256))[t];
        __syncthreads();

        // Stage 1: h = relu(x @ w1^T).
        // thread = (cg 0..127 -> cols 2cg,2cg+1 ; kh 0..3 -> K range kh*64..+63)
        {
            int cg = t & 127;
            int kh = t >> 7;
            int kbase = kh * 64;
            float2 acc[8];
            #pragma unroll
            for (int r = 0; r < 8; r++) acc[r] = make_float2(0.f, 0.f);

            #pragma unroll 4
            for (int kc = 0; kc < 16; kc++) {
                int kk = kbase + kc * 4;
                float4 xv[8];
                #pragma unroll
                for (int r = 0; r < 8; r++)
                    xv[r] = *(const float4*)&xs[r * 256 + kk];   // broadcast LDS
                #pragma unroll
                for (int j = 0; j < 4; j++) {
                    float2 wv = *(const float2*)&w1t[(kk + j) * 256 + cg * 2]; // coalesced
                    #pragma unroll
                    for (int r = 0; r < 8; r++) {
                        float xj = (j == 0) ? xv[r].x : (j == 1) ? xv[r].y
                                 : (j == 2) ? xv[r].z : xv[r].w;
                        acc[r].x = fmaf(wv.x, xj, acc[r].x);
                        acc[r].y = fmaf(wv.y, xj, acc[r].y);
                    }
                }
            }
            #pragma unroll
            for (int r = 0; r < 8; r++)
                *(float2*)&ps[kh * 2048 + r * 256 + cg * 2] = acc[r];
        }
        __syncthreads();

        // reduce 4 K-partials -> hs (+relu)
        #pragma unroll
        for (int i = 0; i < 4; i++) {
            int idx = t + i * 512;
            hs[idx] = fmaxf(ps[idx] + ps[2048 + idx] + ps[4096 + idx] + ps[6144 + idx], 0.f);
        }
        __syncthreads();

        // Stage 2: y = h @ w2^T.
        // thread = (cg 0..63 -> cols 2cg,2cg+1 ; kh 0..7 -> K range kh*32..+31)
        {
            int cg = t & 63;
            int kh = t >> 6;
            int kbase = kh * 32;
            float2 acc[8];
            #pragma unroll
            for (int r = 0; r < 8; r++) acc[r] = make_float2(0.f, 0.f);

            #pragma unroll 4
            for (int kc = 0; kc < 8; kc++) {
                int kk = kbase + kc * 4;
                float4 xv[8];
                #pragma unroll
                for (int r = 0; r < 8; r++)
                    xv[r] = *(const float4*)&hs[r * 256 + kk];   // broadcast LDS
                #pragma unroll
                for (int j = 0; j < 4; j++) {
                    float2 wv = *(const float2*)&w2t[(kk + j) * 128 + cg * 2]; // coalesced
                    #pragma unroll
                    for (int r = 0; r < 8; r++) {
                        float xj = (j == 0) ? xv[r].x : (j == 1) ? xv[r].y
                                 : (j == 2) ? xv[r].z : xv[r].w;
                        acc[r].x = fmaf(wv.x, xj, acc[r].x);
                        acc[r].y = fmaf(wv.y, xj, acc[r].y);
                    }
                }
            }
            #pragma unroll
            for (int r = 0; r < 8; r++)
                *(float2*)&ps[kh * 1024 + r * 128 + cg * 2] = acc[r];
        }
        __syncthreads();

        // reduce 8 K-partials -> ys
        #pragma unroll
        for (int i = 0; i < 2; i++) {
            int idx = t + i * 512;
            float s = ps[idx];
            #pragma unroll
            for (int k = 1; k < 8; k++) s += ps[k * 1024 + idx];
            ys[idx] = s;
        }
        __syncthreads();

        // LayerNorm: warps 0-7, one warp per row.
        if (t < 256) {
            int row  = t >> 5;
            int lane = t & 31;
            float4 v = *(const float4*)&ys[row * 128 + lane * 4];
            float s = v.x + v.y + v.z + v.w;
            float q = v.x * v.x + v.y * v.y + v.z * v.z + v.w * v.w;
            #pragma unroll
            for (int o = 16; o; o >>= 1) {
                s += __shfl_xor_sync(0xFFFFFFFFu, s, o);
                q += __shfl_xor_sync(0xFFFFFFFFu, q, o);
            }
            float mean = s * (1.f / 128.f);
            float var  = q * (1.f / 128.f) - mean * mean;
            float rstd = rsqrtf(var + 1e-5f);
            float4 gv = *(const float4*)&lng[lane * 4];
            float4 bv = *(const float4*)&lnb[lane * 4];
            float* e = g_e[br] + (r0 + row) * 128 + lane * 4;
            e[0] = (v.x - mean) * rstd * gv.x + bv.x;
            e[1] = (v.y - mean) * rstd * gv.y + bv.y;
            e[2] = (v.z - mean) * rstd * gv.z + bv.z;
            e[3] = (v.w - mean) * rstd * gv.w + bv.w;
        }
    }

    // ---------------- Grid-wide barrier ----------------
    __syncthreads();
    __threadfence();
    if (t == 0) {
        atomicAdd(&g_bar0, 1u);
        while (*(volatile unsigned*)&g_bar0 < FUSED_BLOCKS) __nanosleep(64);
    }
    __syncthreads();

    // ---------------- Phase 2: logits ----------------
    {
        int b  = bid / 25;            // batch
        int rt = bid % 25;            // 4-row tile
        float* e1s = pool;            // 4 x 128
        float* e2s = pool + 1024;     // 100 x 68 (stride-68 pad)

        if (t < 128) {
            ((float4*)e1s)[t] = ((const float4*)(g_e[0] + (b * NPATCH + rt * 4) * 128))[t];
        }

        int j = t % 100;
        int r = t / 100;              // 0..3 (valid when t < 400)
        float acc = 0.f;

        #pragma unroll
        for (int kh = 0; kh < 2; kh++) {
            __syncthreads();
            for (int i = t; i < 1600; i += 512) {
                int jj = i >> 4, c4 = i & 15;
                *(float4*)&e2s[jj * 68 + c4 * 4] =
                    *(const float4*)&g_e[1][(b * NPATCH + jj) * 128 + kh * 64 + c4 * 4];
            }
            __syncthreads();
            if (t < 400) {
                const float* e1k = e1s + r * 128 + kh * 64;
                const float* e2k = e2s + j * 68;
                #pragma unroll
                for (int k4 = 0; k4 < 16; k4++) {
                    float4 av = *(const float4*)&e1k[k4 * 4];
                    float4 bv = *(const float4*)&e2k[k4 * 4];
                    acc = fmaf(av.x, bv.x, acc);
                    acc = fmaf(av.y, bv.y, acc);
                    acc = fmaf(av.z, bv.z, acc);
                    acc = fmaf(av.w, bv.w, acc);
                }
            }
        }

        if (t < 400) {
            float s  = expf(lsc[0]);
            int  gi  = rt * 4 + r;
            float v  = s * acc;
            out[b * 10000 + gi * 100 + j]          = v;   // logits_per_img
            out[40000 + b * 10000 + j * 100 + gi]  = v;   // logits_per_depth
        }
    }

    // ---------------- Reset barrier state for next replay ----------------
    __syncthreads();
    __threadfence();
    if (t == 0) {
        unsigned d = atomicAdd(&g_bar1, 1u) + 1u;
        if (d == FUSED_BLOCKS) {
            g_bar0 = 0u;
            g_bar1 = 0u;
            __threadfence();
        }
    }
}

// ---------------------------------------------------------------------------
extern "C" void kernel_launch(void* const* d_in, const int* in_sizes, int n_in,
                              void* d_out, int out_size)
{
    const float* feat_c1      = (const float*)d_in[0];
    const float* feat_c2      = (const float*)d_in[1];
    // d_in[2] = mask_c1 (all ones; grid hardcoded nv=nh=10)
    const float* img_conv_w   = (const float*)d_in[3];
    const float* img_conv_b   = (const float*)d_in[4];
    const float* img_w1       = (const float*)d_in[5];
    const float* img_w2       = (const float*)d_in[6];
    const float* img_ln_g     = (const float*)d_in[7];
    const float* img_ln_b     = (const float*)d_in[8];
    const float* depth_conv_w = (const float*)d_in[9];
    const float* depth_conv_b = (const float*)d_in[10];
    const float* depth_w1     = (const float*)d_in[11];
    const float* depth_w2     = (const float*)d_in[12];
    const float* depth_ln_g   = (const float*)d_in[13];
    const float* depth_ln_b   = (const float*)d_in[14];
    const float* logit_scale  = (const float*)d_in[15];
    float* out = (float*)d_out;

    conv_kernel<<<1604, 256>>>(feat_c1, feat_c2,
                               img_conv_w, img_conv_b,
                               depth_conv_w, depth_conv_b,
                               img_w1, depth_w1, img_w2, depth_w2);

    fused_kernel<<<FUSED_BLOCKS, 512>>>(img_ln_g, img_ln_b,
                                        depth_ln_g, depth_ln_b,
                                        logit_scale, out);
}

// round 14
// speedup vs baseline: 2.1968x; 2.1968x over previous
#include <cuda_runtime.h>
#include <math.h>

#define BATCH 4
#define CCH 256
#define HH 160
#define WW 160
#define NV 10
#define NH 10
#define NPATCH 100     // NV*NH
#define ENC 128
#define NROWS (BATCH*NPATCH)   // 400
#define FUSED_BLOCKS 100
#define TR_BLOCKS 192          // 64+64+32+32 one-tile transpose blocks

// Scratch
__device__ float g_x[2][NROWS * 256];     // conv outputs (patch-flattened)
__device__ float g_e[2][NROWS * ENC];     // embeddings
__device__ float g_w1t[2][256 * 256];     // w1 transposed: [k][col]
__device__ float g_w2t[2][256 * 128];     // w2 transposed: [k][col]
__device__ unsigned g_bar0;               // inter-phase barrier
__device__ unsigned g_bar1;               // exit counter for reset

// ---------------------------------------------------------------------------
// One-tile transpose: 32x32 tile of out[N][M] = in[M][N]^T.  256 threads.
// ---------------------------------------------------------------------------
__device__ void transpose_tile(const float* __restrict__ in, float* __restrict__ out,
                               int M, int N, int tidx)
{
    __shared__ float tile[32][33];
    int tx = threadIdx.x & 31;
    int ty = threadIdx.x >> 5;          // 0..7
    int m0 = (tidx / (N / 32)) * 32;
    int n0 = (tidx % (N / 32)) * 32;
    #pragma unroll
    for (int r = ty; r < 32; r += 8)
        tile[r][tx] = in[(m0 + r) * N + n0 + tx];
    __syncthreads();
    #pragma unroll
    for (int r = ty; r < 32; r += 8)
        out[(n0 + r) * M + m0 + tx] = tile[tx][r];
}

// ---------------------------------------------------------------------------
// Kernel A: blocks 0..191 = weight-transpose tiles (hidden under conv);
// blocks 192..1791 = 1x1 conv (C=256 -> 1) + bias + relu (HBM-saturated
// ~6.1 TB/s, measured ceiling).
// ---------------------------------------------------------------------------
__global__ void __launch_bounds__(256) conv_kernel(
    const float* __restrict__ feat1, const float* __restrict__ feat2,
    const float* __restrict__ cw1, const float* __restrict__ cb1,
    const float* __restrict__ cw2, const float* __restrict__ cb2,
    const float* __restrict__ w1a, const float* __restrict__ w1b,
    const float* __restrict__ w2a, const float* __restrict__ w2b)
{
    if (blockIdx.x < TR_BLOCKS) {
        int which = blockIdx.x;
        if      (which < 64)  transpose_tile(w1a, g_w1t[0], 256, 256, which);
        else if (which < 128) transpose_tile(w1b, g_w1t[1], 256, 256, which - 64);
        else if (which < 160) transpose_tile(w2a, g_w2t[0], 128, 256, which - 128);
        else                  transpose_tile(w2b, g_w2t[1], 128, 256, which - 160);
        return;
    }

    __shared__ float  cw[CCH];
    __shared__ float4 part[256];

    int o0 = (blockIdx.x - TR_BLOCKS) * 32;
    int f  = o0 / 25600;
    const float* feat = f ? feat2 : feat1;
    if (threadIdx.x < CCH) cw[threadIdx.x] = (f ? cw2 : cw1)[threadIdx.x];
    __syncthreads();

    int wi    = threadIdx.x & 31;
    int chunk = threadIdx.x >> 5;

    int rem = (o0 + wi) % 25600;
    int b   = rem / 6400;
    int r2  = rem % 6400;
    int h   = r2 / 40;
    int w0  = (r2 % 40) * 4;

    const int cstride = HH * WW / 4;
    const float4* src = (const float4*)(feat + (size_t)b * CCH * HH * WW + h * WW + w0)
                        + (size_t)chunk * 32 * cstride;

    float4 acc = make_float4(0.f, 0.f, 0.f, 0.f);
    #pragma unroll
    for (int c = 0; c < 32; c++) {
        float4 v = src[c * cstride];
        float wv = cw[chunk * 32 + c];
        acc.x = fmaf(v.x, wv, acc.x);
        acc.y = fmaf(v.y, wv, acc.y);
        acc.z = fmaf(v.z, wv, acc.z);
        acc.w = fmaf(v.w, wv, acc.w);
    }
    part[threadIdx.x] = acc;
    __syncthreads();

    if (threadIdx.x < 32) {
        float4 a = part[threadIdx.x];
        #pragma unroll
        for (int k = 1; k < 8; k++) {
            float4 p = part[threadIdx.x + k * 32];
            a.x += p.x; a.y += p.y; a.z += p.z; a.w += p.w;
        }
        float cb = f ? cb2[0] : cb1[0];
        a.x = fmaxf(a.x + cb, 0.f);
        a.y = fmaxf(a.y + cb, 0.f);
        a.z = fmaxf(a.z + cb, 0.f);
        a.w = fmaxf(a.w + cb, 0.f);

        int p   = b * NPATCH + (h >> 4) * NH + (w0 >> 4);
        int idx = (h & 15) * 16 + (w0 & 15);
        *(float4*)&g_x[f][p * 256 + idx] = a;
    }
}

// ---------------------------------------------------------------------------
// Kernel B (fused, 512 threads): fc1 + fc2 + LN | grid barrier | logits.
// Coalesced weight reads via transposed weights (measured 21.7us, L1 21%).
// smem pool 48KB: xs[0:2048) hs[2048:4096) ps[4096:12288)
//   phase2: e1s pool[0:512), e2s pool[1024:7824)
// ---------------------------------------------------------------------------
__global__ void __launch_bounds__(512) fused_kernel(
    const float* __restrict__ ga,  const float* __restrict__ ba,
    const float* __restrict__ gb,  const float* __restrict__ bb,
    const float* __restrict__ lsc, float* __restrict__ out)
{
    __shared__ float pool[12288];   // 48 KB

    float* xs = pool;               // 8 x 256
    float* hs = pool + 2048;        // 8 x 256
    float* ps = pool + 4096;        // partials: 4x[8][256] (s1) / 8x[8][128] (s2)
    float* ys = pool;               // fc2 out 8x128 (aliases xs, dead by then)

    int t   = threadIdx.x;
    int bid = blockIdx.x;           // 0..99

    // ---------------- Phase 1: FC + LayerNorm ----------------
    {
        int br = bid / 50;
        int r0 = (bid % 50) * 8;
        const float* lng = br ? gb : ga;
        const float* lnb = br ? bb : ba;
        const float* w1t = g_w1t[br];
        const float* w2t = g_w2t[br];

        // load 8x256 input rows (512 float4, 1 per thread)
        ((float4*)xs)[t] = ((const float4*)(g_x[br] + r0 * 256))[t];
        __syncthreads();

        // Stage 1: h = relu(x @ w1^T).
        // thread = (cg 0..127 -> cols 2cg,2cg+1 ; kh 0..3 -> K range kh*64..+63)
        {
            int cg = t & 127;
            int kh = t >> 7;
            int kbase = kh * 64;
            float2 acc[8];
            #pragma unroll
            for (int r = 0; r < 8; r++) acc[r] = make_float2(0.f, 0.f);

            #pragma unroll 4
            for (int kc = 0; kc < 16; kc++) {
                int kk = kbase + kc * 4;
                float4 xv[8];
                #pragma unroll
                for (int r = 0; r < 8; r++)
                    xv[r] = *(const float4*)&xs[r * 256 + kk];   // broadcast LDS
                #pragma unroll
                for (int j = 0; j < 4; j++) {
                    float2 wv = *(const float2*)&w1t[(kk + j) * 256 + cg * 2]; // coalesced
                    #pragma unroll
                    for (int r = 0; r < 8; r++) {
                        float xj = (j == 0) ? xv[r].x : (j == 1) ? xv[r].y
                                 : (j == 2) ? xv[r].z : xv[r].w;
                        acc[r].x = fmaf(wv.x, xj, acc[r].x);
                        acc[r].y = fmaf(wv.y, xj, acc[r].y);
                    }
                }
            }
            #pragma unroll
            for (int r = 0; r < 8; r++)
                *(float2*)&ps[kh * 2048 + r * 256 + cg * 2] = acc[r];
        }
        __syncthreads();

        // reduce 4 K-partials -> hs (+relu)
        #pragma unroll
        for (int i = 0; i < 4; i++) {
            int idx = t + i * 512;
            hs[idx] = fmaxf(ps[idx] + ps[2048 + idx] + ps[4096 + idx] + ps[6144 + idx], 0.f);
        }
        __syncthreads();

        // Stage 2: y = h @ w2^T.
        // thread = (cg 0..63 -> cols 2cg,2cg+1 ; kh 0..7 -> K range kh*32..+31)
        {
            int cg = t & 63;
            int kh = t >> 6;
            int kbase = kh * 32;
            float2 acc[8];
            #pragma unroll
            for (int r = 0; r < 8; r++) acc[r] = make_float2(0.f, 0.f);

            #pragma unroll 4
            for (int kc = 0; kc < 8; kc++) {
                int kk = kbase + kc * 4;
                float4 xv[8];
                #pragma unroll
                for (int r = 0; r < 8; r++)
                    xv[r] = *(const float4*)&hs[r * 256 + kk];   // broadcast LDS
                #pragma unroll
                for (int j = 0; j < 4; j++) {
                    float2 wv = *(const float2*)&w2t[(kk + j) * 128 + cg * 2]; // coalesced
                    #pragma unroll
                    for (int r = 0; r < 8; r++) {
                        float xj = (j == 0) ? xv[r].x : (j == 1) ? xv[r].y
                                 : (j == 2) ? xv[r].z : xv[r].w;
                        acc[r].x = fmaf(wv.x, xj, acc[r].x);
                        acc[r].y = fmaf(wv.y, xj, acc[r].y);
                    }
                }
            }
            #pragma unroll
            for (int r = 0; r < 8; r++)
                *(float2*)&ps[kh * 1024 + r * 128 + cg * 2] = acc[r];
        }
        __syncthreads();

        // reduce 8 K-partials -> ys
        #pragma unroll
        for (int i = 0; i < 2; i++) {
            int idx = t + i * 512;
            float s = ps[idx];
            #pragma unroll
            for (int k = 1; k < 8; k++) s += ps[k * 1024 + idx];
            ys[idx] = s;
        }
        __syncthreads();

        // LayerNorm: warps 0-7, one warp per row.
        if (t < 256) {
            int row  = t >> 5;
            int lane = t & 31;
            float4 v = *(const float4*)&ys[row * 128 + lane * 4];
            float s = v.x + v.y + v.z + v.w;
            float q = v.x * v.x + v.y * v.y + v.z * v.z + v.w * v.w;
            #pragma unroll
            for (int o = 16; o; o >>= 1) {
                s += __shfl_xor_sync(0xFFFFFFFFu, s, o);
                q += __shfl_xor_sync(0xFFFFFFFFu, q, o);
            }
            float mean = s * (1.f / 128.f);
            float var  = q * (1.f / 128.f) - mean * mean;
            float rstd = rsqrtf(var + 1e-5f);
            float4 gv = *(const float4*)&lng[lane * 4];
            float4 bv = *(const float4*)&lnb[lane * 4];
            float* e = g_e[br] + (r0 + row) * 128 + lane * 4;
            e[0] = (v.x - mean) * rstd * gv.x + bv.x;
            e[1] = (v.y - mean) * rstd * gv.y + bv.y;
            e[2] = (v.z - mean) * rstd * gv.z + bv.z;
            e[3] = (v.w - mean) * rstd * gv.w + bv.w;
        }
    }

    // ---------------- Grid-wide barrier ----------------
    __syncthreads();
    __threadfence();
    if (t == 0) {
        atomicAdd(&g_bar0, 1u);
        while (*(volatile unsigned*)&g_bar0 < FUSED_BLOCKS) __nanosleep(64);
    }
    __syncthreads();

    // ---------------- Phase 2: logits ----------------
    {
        int b  = bid / 25;            // batch
        int rt = bid % 25;            // 4-row tile
        float* e1s = pool;            // 4 x 128
        float* e2s = pool + 1024;     // 100 x 68 (stride-68 pad)

        if (t < 128) {
            ((float4*)e1s)[t] = ((const float4*)(g_e[0] + (b * NPATCH + rt * 4) * 128))[t];
        }

        int j = t % 100;
        int r = t / 100;              // 0..3 (valid when t < 400)
        float acc = 0.f;

        #pragma unroll
        for (int kh = 0; kh < 2; kh++) {
            __syncthreads();
            for (int i = t; i < 1600; i += 512) {
                int jj = i >> 4, c4 = i & 15;
                *(float4*)&e2s[jj * 68 + c4 * 4] =
                    *(const float4*)&g_e[1][(b * NPATCH + jj) * 128 + kh * 64 + c4 * 4];
            }
            __syncthreads();
            if (t < 400) {
                const float* e1k = e1s + r * 128 + kh * 64;
                const float* e2k = e2s + j * 68;
                #pragma unroll
                for (int k4 = 0; k4 < 16; k4++) {
                    float4 av = *(const float4*)&e1k[k4 * 4];
                    float4 bv = *(const float4*)&e2k[k4 * 4];
                    acc = fmaf(av.x, bv.x, acc);
                    acc = fmaf(av.y, bv.y, acc);
                    acc = fmaf(av.z, bv.z, acc);
                    acc = fmaf(av.w, bv.w, acc);
                }
            }
        }

        if (t < 400) {
            float s  = expf(lsc[0]);
            int  gi  = rt * 4 + r;
            float v  = s * acc;
            out[b * 10000 + gi * 100 + j]          = v;   // logits_per_img
            out[40000 + b * 10000 + j * 100 + gi]  = v;   // logits_per_depth
        }
    }

    // ---------------- Reset barrier state for next replay ----------------
    __syncthreads();
    __threadfence();
    if (t == 0) {
        unsigned d = atomicAdd(&g_bar1, 1u) + 1u;
        if (d == FUSED_BLOCKS) {
            g_bar0 = 0u;
            g_bar1 = 0u;
            __threadfence();
        }
    }
}

// ---------------------------------------------------------------------------
extern "C" void kernel_launch(void* const* d_in, const int* in_sizes, int n_in,
                              void* d_out, int out_size)
{
    const float* feat_c1      = (const float*)d_in[0];
    const float* feat_c2      = (const float*)d_in[1];
    // d_in[2] = mask_c1 (all ones; grid hardcoded nv=nh=10)
    const float* img_conv_w   = (const float*)d_in[3];
    const float* img_conv_b   = (const float*)d_in[4];
    const float* img_w1       = (const float*)d_in[5];
    const float* img_w2       = (const float*)d_in[6];
    const float* img_ln_g     = (const float*)d_in[7];
    const float* img_ln_b     = (const float*)d_in[8];
    const float* depth_conv_w = (const float*)d_in[9];
    const float* depth_conv_b = (const float*)d_in[10];
    const float* depth_w1     = (const float*)d_in[11];
    const float* depth_w2     = (const float*)d_in[12];
    const float* depth_ln_g   = (const float*)d_in[13];
    const float* depth_ln_b   = (const float*)d_in[14];
    const float* logit_scale  = (const float*)d_in[15];
    float* out = (float*)d_out;

    conv_kernel<<<1600 + TR_BLOCKS, 256>>>(feat_c1, feat_c2,
                                           img_conv_w, img_conv_b,
                                           depth_conv_w, depth_conv_b,
                                           img_w1, depth_w1, img_w2, depth_w2);

    fused_kernel<<<FUSED_BLOCKS, 512>>>(img_ln_g, img_ln_b,
                                        depth_ln_g, depth_ln_b,
                                        logit_scale, out);
}

// round 16
// speedup vs baseline: 2.2684x; 1.0326x over previous
#include <cuda_runtime.h>
#include <math.h>

#define BATCH 4
#define CCH 256
#define HH 160
#define WW 160
#define NV 10
#define NH 10
#define NPATCH 100     // NV*NH
#define ENC 128
#define NROWS (BATCH*NPATCH)   // 400
#define FUSED_BLOCKS 200       // must stay co-resident: 2 blocks/SM x 148 SMs >= 200
#define TR_BLOCKS 192          // 64+64+32+32 one-tile transpose blocks

// Scratch
__device__ float g_x[2][NROWS * 256];     // conv outputs (patch-flattened)
__device__ float g_e[2][NROWS * ENC];     // embeddings
__device__ float g_w1t[2][256 * 256];     // w1 transposed: [k][col]
__device__ float g_w2t[2][256 * 128];     // w2 transposed: [k][col]
__device__ unsigned g_bar0;               // inter-phase barrier
__device__ unsigned g_bar1;               // exit counter for reset

// ---------------------------------------------------------------------------
// One-tile transpose: 32x32 tile of out[N][M] = in[M][N]^T.  256 threads.
// ---------------------------------------------------------------------------
__device__ void transpose_tile(const float* __restrict__ in, float* __restrict__ out,
                               int M, int N, int tidx)
{
    __shared__ float tile[32][33];
    int tx = threadIdx.x & 31;
    int ty = threadIdx.x >> 5;          // 0..7
    int m0 = (tidx / (N / 32)) * 32;
    int n0 = (tidx % (N / 32)) * 32;
    #pragma unroll
    for (int r = ty; r < 32; r += 8)
        tile[r][tx] = in[(m0 + r) * N + n0 + tx];
    __syncthreads();
    #pragma unroll
    for (int r = ty; r < 32; r += 8)
        out[(n0 + r) * M + m0 + tx] = tile[tx][r];
}

// ---------------------------------------------------------------------------
// Kernel A: blocks 0..191 = weight-transpose tiles (hidden under conv);
// blocks 192..1791 = 1x1 conv (C=256 -> 1) + bias + relu (HBM-saturated
// ~6.1 TB/s, measured ceiling).
// ---------------------------------------------------------------------------
__global__ void __launch_bounds__(256) conv_kernel(
    const float* __restrict__ feat1, const float* __restrict__ feat2,
    const float* __restrict__ cw1, const float* __restrict__ cb1,
    const float* __restrict__ cw2, const float* __restrict__ cb2,
    const float* __restrict__ w1a, const float* __restrict__ w1b,
    const float* __restrict__ w2a, const float* __restrict__ w2b)
{
    if (blockIdx.x < TR_BLOCKS) {
        int which = blockIdx.x;
        if      (which < 64)  transpose_tile(w1a, g_w1t[0], 256, 256, which);
        else if (which < 128) transpose_tile(w1b, g_w1t[1], 256, 256, which - 64);
        else if (which < 160) transpose_tile(w2a, g_w2t[0], 128, 256, which - 128);
        else                  transpose_tile(w2b, g_w2t[1], 128, 256, which - 160);
        return;
    }

    __shared__ float  cw[CCH];
    __shared__ float4 part[256];

    int o0 = (blockIdx.x - TR_BLOCKS) * 32;
    int f  = o0 / 25600;
    const float* feat = f ? feat2 : feat1;
    if (threadIdx.x < CCH) cw[threadIdx.x] = (f ? cw2 : cw1)[threadIdx.x];
    __syncthreads();

    int wi    = threadIdx.x & 31;
    int chunk = threadIdx.x >> 5;

    int rem = (o0 + wi) % 25600;
    int b   = rem / 6400;
    int r2  = rem % 6400;
    int h   = r2 / 40;
    int w0  = (r2 % 40) * 4;

    const int cstride = HH * WW / 4;
    const float4* src = (const float4*)(feat + (size_t)b * CCH * HH * WW + h * WW + w0)
                        + (size_t)chunk * 32 * cstride;

    float4 acc = make_float4(0.f, 0.f, 0.f, 0.f);
    #pragma unroll
    for (int c = 0; c < 32; c++) {
        float4 v = src[c * cstride];
        float wv = cw[chunk * 32 + c];
        acc.x = fmaf(v.x, wv, acc.x);
        acc.y = fmaf(v.y, wv, acc.y);
        acc.z = fmaf(v.z, wv, acc.z);
        acc.w = fmaf(v.w, wv, acc.w);
    }
    part[threadIdx.x] = acc;
    __syncthreads();

    if (threadIdx.x < 32) {
        float4 a = part[threadIdx.x];
        #pragma unroll
        for (int k = 1; k < 8; k++) {
            float4 p = part[threadIdx.x + k * 32];
            a.x += p.x; a.y += p.y; a.z += p.z; a.w += p.w;
        }
        float cb = f ? cb2[0] : cb1[0];
        a.x = fmaxf(a.x + cb, 0.f);
        a.y = fmaxf(a.y + cb, 0.f);
        a.z = fmaxf(a.z + cb, 0.f);
        a.w = fmaxf(a.w + cb, 0.f);

        int p   = b * NPATCH + (h >> 4) * NH + (w0 >> 4);
        int idx = (h & 15) * 16 + (w0 & 15);
        *(float4*)&g_x[f][p * 256 + idx] = a;
    }
}

// ---------------------------------------------------------------------------
// Kernel B (fused, 512 threads, 200 blocks, 2 blocks/SM): fc1 + fc2 + LN |
// grid barrier | logits.  4 rows per block.  Coalesced transposed-weight
// reads.  __launch_bounds__(512,2) caps regs at 64 so ALL 200 blocks are
// co-resident (spin barrier deadlock-free: 148 SMs x 2 = 296 >= 200).
// smem pool 32KB: xs[0:1024) hs[1024:2048) ps[2048:6144)
//   phase2: e1s pool[0:256), e2s pool[512:7312)
// ---------------------------------------------------------------------------
__global__ void __launch_bounds__(512, 2) fused_kernel(
    const float* __restrict__ ga,  const float* __restrict__ ba,
    const float* __restrict__ gb,  const float* __restrict__ bb,
    const float* __restrict__ lsc, float* __restrict__ out)
{
    __shared__ float pool[8192];    // 32 KB

    float* xs = pool;               // 4 x 256
    float* hs = pool + 1024;        // 4 x 256
    float* ps = pool + 2048;        // partials: 4x[4][256] (s1) / 8x[4][128] (s2)
    float* ys = pool;               // fc2 out 4x128 (aliases xs, dead by then)

    int t   = threadIdx.x;
    int bid = blockIdx.x;           // 0..199

    // ---------------- Phase 1: FC + LayerNorm ----------------
    {
        int br = bid / 100;
        int r0 = (bid % 100) * 4;
        const float* lng = br ? gb : ga;
        const float* lnb = br ? bb : ba;
        const float* w1t = g_w1t[br];
        const float* w2t = g_w2t[br];

        // load 4x256 input rows (256 float4)
        if (t < 256)
            ((float4*)xs)[t] = ((const float4*)(g_x[br] + r0 * 256))[t];
        __syncthreads();

        // Stage 1: h = relu(x @ w1^T).
        // thread = (cg 0..127 -> cols 2cg,2cg+1 ; kh 0..3 -> K range kh*64..+63)
        {
            int cg = t & 127;
            int kh = t >> 7;
            int kbase = kh * 64;
            float2 acc[4];
            #pragma unroll
            for (int r = 0; r < 4; r++) acc[r] = make_float2(0.f, 0.f);

            #pragma unroll 4
            for (int kc = 0; kc < 16; kc++) {
                int kk = kbase + kc * 4;
                float4 xv[4];
                #pragma unroll
                for (int r = 0; r < 4; r++)
                    xv[r] = *(const float4*)&xs[r * 256 + kk];   // broadcast LDS
                #pragma unroll
                for (int j = 0; j < 4; j++) {
                    float2 wv = *(const float2*)&w1t[(kk + j) * 256 + cg * 2]; // coalesced
                    #pragma unroll
                    for (int r = 0; r < 4; r++) {
                        float xj = (j == 0) ? xv[r].x : (j == 1) ? xv[r].y
                                 : (j == 2) ? xv[r].z : xv[r].w;
                        acc[r].x = fmaf(wv.x, xj, acc[r].x);
                        acc[r].y = fmaf(wv.y, xj, acc[r].y);
                    }
                }
            }
            #pragma unroll
            for (int r = 0; r < 4; r++)
                *(float2*)&ps[kh * 1024 + r * 256 + cg * 2] = acc[r];
        }
        __syncthreads();

        // reduce 4 K-partials -> hs (+relu)   (1024 entries)
        {
            int idx = t;
            if (t < 512) {   // always true; keeps symmetry
                #pragma unroll
                for (int i = 0; i < 2; i++) {
                    int id2 = idx + i * 512;
                    hs[id2] = fmaxf(ps[id2] + ps[1024 + id2] + ps[2048 + id2] + ps[3072 + id2], 0.f);
                }
            }
        }
        __syncthreads();

        // Stage 2: y = h @ w2^T.
        // thread = (cg 0..63 -> cols 2cg,2cg+1 ; kh 0..7 -> K range kh*32..+31)
        {
            int cg = t & 63;
            int kh = t >> 6;
            int kbase = kh * 32;
            float2 acc[4];
            #pragma unroll
            for (int r = 0; r < 4; r++) acc[r] = make_float2(0.f, 0.f);

            #pragma unroll 4
            for (int kc = 0; kc < 8; kc++) {
                int kk = kbase + kc * 4;
                float4 xv[4];
                #pragma unroll
                for (int r = 0; r < 4; r++)
                    xv[r] = *(const float4*)&hs[r * 256 + kk];   // broadcast LDS
                #pragma unroll
                for (int j = 0; j < 4; j++) {
                    float2 wv = *(const float2*)&w2t[(kk + j) * 128 + cg * 2]; // coalesced
                    #pragma unroll
                    for (int r = 0; r < 4; r++) {
                        float xj = (j == 0) ? xv[r].x : (j == 1) ? xv[r].y
                                 : (j == 2) ? xv[r].z : xv[r].w;
                        acc[r].x = fmaf(wv.x, xj, acc[r].x);
                        acc[r].y = fmaf(wv.y, xj, acc[r].y);
                    }
                }
            }
            #pragma unroll
            for (int r = 0; r < 4; r++)
                *(float2*)&ps[kh * 512 + r * 128 + cg * 2] = acc[r];
        }
        __syncthreads();

        // reduce 8 K-partials -> ys  (512 entries)
        {
            float s = ps[t];
            #pragma unroll
            for (int k = 1; k < 8; k++) s += ps[k * 512 + t];
            ys[t] = s;
        }
        __syncthreads();

        // LayerNorm: warps 0-3, one warp per row.
        if (t < 128) {
            int row  = t >> 5;
            int lane = t & 31;
            float4 v = *(const float4*)&ys[row * 128 + lane * 4];
            float s = v.x + v.y + v.z + v.w;
            float q = v.x * v.x + v.y * v.y + v.z * v.z + v.w * v.w;
            #pragma unroll
            for (int o = 16; o; o >>= 1) {
                s += __shfl_xor_sync(0xFFFFFFFFu, s, o);
                q += __shfl_xor_sync(0xFFFFFFFFu, q, o);
            }
            float mean = s * (1.f / 128.f);
            float var  = q * (1.f / 128.f) - mean * mean;
            float rstd = rsqrtf(var + 1e-5f);
            float4 gv = *(const float4*)&lng[lane * 4];
            float4 bv = *(const float4*)&lnb[lane * 4];
            float* e = g_e[br] + (r0 + row) * 128 + lane * 4;
            e[0] = (v.x - mean) * rstd * gv.x + bv.x;
            e[1] = (v.y - mean) * rstd * gv.y + bv.y;
            e[2] = (v.z - mean) * rstd * gv.z + bv.z;
            e[3] = (v.w - mean) * rstd * gv.w + bv.w;
        }
    }

    // ---------------- Grid-wide barrier ----------------
    __syncthreads();
    __threadfence();
    if (t == 0) {
        atomicAdd(&g_bar0, 1u);
        while (*(volatile unsigned*)&g_bar0 < FUSED_BLOCKS) __nanosleep(64);
    }
    __syncthreads();

    // ---------------- Phase 2: logits ----------------
    {
        int b  = bid / 50;            // batch
        int rt = bid % 50;            // 2-row tile
        float* e1s = pool;            // 2 x 128
        float* e2s = pool + 512;      // 100 x 68 (stride-68 pad)

        if (t < 64) {
            ((float4*)e1s)[t] = ((const float4*)(g_e[0] + (b * NPATCH + rt * 2) * 128))[t];
        }

        int j = t % 100;
        int r = t / 100;              // 0..1 (valid when t < 200)
        float acc = 0.f;

        #pragma unroll
        for (int kh = 0; kh < 2; kh++) {
            __syncthreads();
            for (int i = t; i < 1600; i += 512) {
                int jj = i >> 4, c4 = i & 15;
                *(float4*)&e2s[jj * 68 + c4 * 4] =
                    *(const float4*)&g_e[1][(b * NPATCH + jj) * 128 + kh * 64 + c4 * 4];
            }
            __syncthreads();
            if (t < 200) {
                const float* e1k = e1s + r * 128 + kh * 64;
                const float* e2k = e2s + j * 68;
                #pragma unroll
                for (int k4 = 0; k4 < 16; k4++) {
                    float4 av = *(const float4*)&e1k[k4 * 4];
                    float4 bv = *(const float4*)&e2k[k4 * 4];
                    acc = fmaf(av.x, bv.x, acc);
                    acc = fmaf(av.y, bv.y, acc);
                    acc = fmaf(av.z, bv.z, acc);
                    acc = fmaf(av.w, bv.w, acc);
                }
            }
        }

        if (t < 200) {
            float s  = expf(lsc[0]);
            int  gi  = rt * 2 + r;
            float v  = s * acc;
            out[b * 10000 + gi * 100 + j]          = v;   // logits_per_img
            out[40000 + b * 10000 + j * 100 + gi]  = v;   // logits_per_depth
        }
    }

    // ---------------- Reset barrier state for next replay ----------------
    __syncthreads();
    __threadfence();
    if (t == 0) {
        unsigned d = atomicAdd(&g_bar1, 1u) + 1u;
        if (d == FUSED_BLOCKS) {
            g_bar0 = 0u;
            g_bar1 = 0u;
            __threadfence();
        }
    }
}

// ---------------------------------------------------------------------------
extern "C" void kernel_launch(void* const* d_in, const int* in_sizes, int n_in,
                              void* d_out, int out_size)
{
    const float* feat_c1      = (const float*)d_in[0];
    const float* feat_c2      = (const float*)d_in[1];
    // d_in[2] = mask_c1 (all ones; grid hardcoded nv=nh=10)
    const float* img_conv_w   = (const float*)d_in[3];
    const float* img_conv_b   = (const float*)d_in[4];
    const float* img_w1       = (const float*)d_in[5];
    const float* img_w2       = (const float*)d_in[6];
    const float* img_ln_g     = (const float*)d_in[7];
    const float* img_ln_b     = (const float*)d_in[8];
    const float* depth_conv_w = (const float*)d_in[9];
    const float* depth_conv_b = (const float*)d_in[10];
    const float* depth_w1     = (const float*)d_in[11];
    const float* depth_w2     = (const float*)d_in[12];
    const float* depth_ln_g   = (const float*)d_in[13];
    const float* depth_ln_b   = (const float*)d_in[14];
    const float* logit_scale  = (const float*)d_in[15];
    float* out = (float*)d_out;

    conv_kernel<<<1600 + TR_BLOCKS, 256>>>(feat_c1, feat_c2,
                                           img_conv_w, img_conv_b,
                                           depth_conv_w, depth_conv_b,
                                           img_w1, depth_w1, img_w2, depth_w2);

    fused_kernel<<<FUSED_BLOCKS, 512>>>(img_ln_g, img_ln_b,
                                        depth_ln_g, depth_ln_b,
                                        logit_scale, out);
}